// round 3
// baseline (speedup 1.0000x reference)
#include <cuda_runtime.h>
#include <cstdint>

#define THREADS 160
#define NTILE   136        // 16*17/2 upper-triangle 4x4 tiles
#define FDIM    64
#define EDIM    32
#define ECHUNK  16         // e-chunk size for Ydup
#define NCHUNK  (EDIM / ECHUNK)

// dynamic smem (bytes):
//   Xt   : EDIM * FDIM floats          = 8192 B   (Xt[e][f] = x[f,e], plain)
//   Ydup : 5 * ECHUNK * FDIM ull       = 40960 B  (dup pairs (y,y), y = x[i,e]*w[e,a])
#define XT_FLOATS   (EDIM * FDIM)
#define YDUP_ULLS   (5 * ECHUNK * FDIM)
#define SMEM_BYTES  (XT_FLOATS * 4 + YDUP_ULLS * 8)

typedef unsigned long long ull;

static __device__ __forceinline__ ull pk2(float lo, float hi) {
    ull r;
    asm("mov.b64 %0, {%1, %2};" : "=l"(r) : "f"(lo), "f"(hi));
    return r;
}
static __device__ __forceinline__ float2 upk2(ull v) {
    float2 r;
    asm("mov.b64 {%0, %1}, %2;" : "=f"(r.x), "=f"(r.y) : "l"(v));
    return r;
}
static __device__ __forceinline__ ull fma2_(ull a, ull b, ull c) {
    ull d;
    asm("fma.rn.f32x2 %0, %1, %2, %3;" : "=l"(d) : "l"(a), "l"(b), "l"(c));
    return d;
}

__global__ void __launch_bounds__(THREADS, 3)
afm_kernel(const float* __restrict__ x,
           const float* __restrict__ attn_w,
           const float* __restrict__ attn_b,
           const float* __restrict__ attn_h,
           const float* __restrict__ pool_w,
           const float* __restrict__ pool_b,
           float* __restrict__ out)
{
    extern __shared__ __align__(16) char sm[];
    float* Xt   = reinterpret_cast<float*>(sm);                 // [EDIM][FDIM]
    ull*   Ydup = reinterpret_cast<ull*>(sm + XT_FLOATS * 4);   // [5*ECHUNK][FDIM]

    __shared__ float w5[EDIM][8];   // [e][0..3]=attn_w, [e][4]=pool_w
    __shared__ float rmax[5], rse[5], rsq[5];
    __shared__ float bmax;

    const int t = threadIdx.x;
    const int b = blockIdx.x;
    const float* xb = x + (size_t)b * (FDIM * EDIM);

    // ---- load + transpose x[b] into Xt[e][f] (coalesced LDG) ----
    for (int q = t; q < 512; q += THREADS) {
        int f  = q >> 3;            // feature 0..63
        int e4 = q & 7;             // group of 4 e
        float4 v = reinterpret_cast<const float4*>(xb)[q];
        Xt[(e4 * 4 + 0) * FDIM + f] = v.x;
        Xt[(e4 * 4 + 1) * FDIM + f] = v.y;
        Xt[(e4 * 4 + 2) * FDIM + f] = v.z;
        Xt[(e4 * 4 + 3) * FDIM + f] = v.w;
    }
    if (t < EDIM) {
        float4 wv = reinterpret_cast<const float4*>(attn_w)[t];
        w5[t][0] = wv.x; w5[t][1] = wv.y; w5[t][2] = wv.z; w5[t][3] = wv.w;
        w5[t][4] = pool_w[t];
    }

    // ---- thread -> upper-triangle 4x4 tile (ti <= tj) ----
    int k = (t < NTILE) ? t : (NTILE - 1);
    int ti = (int)((33.0f - sqrtf(1089.0f - 8.0f * (float)k)) * 0.5f);
    while (ti > 0 && (33 * ti - ti * ti) / 2 > k) ti--;
    while ((33 * (ti + 1) - (ti + 1) * (ti + 1)) / 2 <= k) ti++;
    int tj = ti + (k - (33 * ti - ti * ti) / 2);
    const int i0 = ti * 4, j0 = tj * 4;

    ull acc[5][4][2];
    #pragma unroll
    for (int a = 0; a < 5; a++)
        #pragma unroll
        for (int ii = 0; ii < 4; ii++) { acc[a][ii][0] = 0ull; acc[a][ii][1] = 0ull; }

    // ---- e-chunked: build Ydup[a][ec][i] = dup(x[i,e]*w[e,a]), then accumulate ----
    for (int c = 0; c < NCHUNK; c++) {
        const int e0 = c * ECHUNK;
        __syncthreads();   // Xt ready (c==0) / previous chunk's reads done (c>0)

        // build: 5*16*64/4 = 1280 float4-units, 8 per thread
        for (int q = t; q < (5 * ECHUNK * FDIM) / 4; q += THREADS) {
            int i4  = q & 15;           // float4 index within row of 64
            int row = q >> 4;           // a*ECHUNK + ec
            int ec  = row & (ECHUNK - 1);
            int a   = row >> 4;
            float4 v = *reinterpret_cast<const float4*>(&Xt[(e0 + ec) * FDIM + i4 * 4]);
            float  w = w5[e0 + ec][a];
            ull* dst = Ydup + row * FDIM + i4 * 4;
            dst[0] = pk2(v.x * w, v.x * w);
            dst[1] = pk2(v.y * w, v.y * w);
            dst[2] = pk2(v.z * w, v.z * w);
            dst[3] = pk2(v.w * w, v.w * w);
        }
        __syncthreads();

        // mainloop over this chunk
        #pragma unroll 2
        for (int ec = 0; ec < ECHUNK; ec++) {
            // j-side: 4 contiguous floats = 2 f32x2 operands, no packing
            ulonglong2 xj = *reinterpret_cast<const ulonglong2*>(&Xt[(e0 + ec) * FDIM + j0]);
            #pragma unroll
            for (int a = 0; a < 5; a++) {
                const ull* yr = Ydup + (a * ECHUNK + ec) * FDIM + i0;
                ulonglong2 c01 = *reinterpret_cast<const ulonglong2*>(yr);
                ulonglong2 c23 = *reinterpret_cast<const ulonglong2*>(yr + 2);
                acc[a][0][0] = fma2_(c01.x, xj.x, acc[a][0][0]);
                acc[a][0][1] = fma2_(c01.x, xj.y, acc[a][0][1]);
                acc[a][1][0] = fma2_(c01.y, xj.x, acc[a][1][0]);
                acc[a][1][1] = fma2_(c01.y, xj.y, acc[a][1][1]);
                acc[a][2][0] = fma2_(c23.x, xj.x, acc[a][2][0]);
                acc[a][2][1] = fma2_(c23.x, xj.y, acc[a][2][1]);
                acc[a][3][0] = fma2_(c23.y, xj.x, acc[a][3][0]);
                acc[a][3][1] = fma2_(c23.y, xj.y, acc[a][3][1]);
            }
        }
    }

    // ---- combine: relu-MLP score, pooled bilinear per pair ----
    const float b0 = attn_b[0], b1 = attn_b[1], b2 = attn_b[2], b3 = attn_b[3];
    const float h0 = attn_h[0], h1 = attn_h[1], h2 = attn_h[2], h3 = attn_h[3];

    float sc[4][4], qc[4][4];
    #pragma unroll
    for (int ii = 0; ii < 4; ii++) {
        #pragma unroll
        for (int jp = 0; jp < 2; jp++) {
            float2 a0 = upk2(acc[0][ii][jp]);
            float2 a1 = upk2(acc[1][ii][jp]);
            float2 a2 = upk2(acc[2][ii][jp]);
            float2 a3 = upk2(acc[3][ii][jp]);
            float2 a4 = upk2(acc[4][ii][jp]);
            sc[ii][jp * 2 + 0] = fmaxf(a0.x + b0, 0.f) * h0 + fmaxf(a1.x + b1, 0.f) * h1
                               + fmaxf(a2.x + b2, 0.f) * h2 + fmaxf(a3.x + b3, 0.f) * h3;
            sc[ii][jp * 2 + 1] = fmaxf(a0.y + b0, 0.f) * h0 + fmaxf(a1.y + b1, 0.f) * h1
                               + fmaxf(a2.y + b2, 0.f) * h2 + fmaxf(a3.y + b3, 0.f) * h3;
            qc[ii][jp * 2 + 0] = a4.x;
            qc[ii][jp * 2 + 1] = a4.y;
        }
    }

    const bool live = (t < NTILE);

    // ---- softmax over i<j cells, fused weighted scalar sum ----
    float lmax = -1e30f;
    #pragma unroll
    for (int ii = 0; ii < 4; ii++)
        #pragma unroll
        for (int jj = 0; jj < 4; jj++)
            if (live && (i0 + ii < j0 + jj)) lmax = fmaxf(lmax, sc[ii][jj]);

    #pragma unroll
    for (int o = 16; o; o >>= 1)
        lmax = fmaxf(lmax, __shfl_xor_sync(0xffffffffu, lmax, o));
    if ((t & 31) == 0) rmax[t >> 5] = lmax;
    __syncthreads();
    if (t == 0) {
        float m = rmax[0];
        #pragma unroll
        for (int i = 1; i < 5; i++) m = fmaxf(m, rmax[i]);
        bmax = m;
    }
    __syncthreads();
    const float m = bmax;

    float se = 0.f, sq = 0.f;
    #pragma unroll
    for (int ii = 0; ii < 4; ii++)
        #pragma unroll
        for (int jj = 0; jj < 4; jj++)
            if (live && (i0 + ii < j0 + jj)) {
                float ex = __expf(sc[ii][jj] - m);
                se += ex;
                sq += ex * qc[ii][jj];
            }

    #pragma unroll
    for (int o = 16; o; o >>= 1) {
        se += __shfl_xor_sync(0xffffffffu, se, o);
        sq += __shfl_xor_sync(0xffffffffu, sq, o);
    }
    if ((t & 31) == 0) { rse[t >> 5] = se; rsq[t >> 5] = sq; }
    __syncthreads();
    if (t == 0) {
        float S = 0.f, Q = 0.f;
        #pragma unroll
        for (int i = 0; i < 5; i++) { S += rse[i]; Q += rsq[i]; }
        out[b] = Q / S + pool_b[0];
    }
}

extern "C" void kernel_launch(void* const* d_in, const int* in_sizes, int n_in,
                              void* d_out, int out_size)
{
    const float* x      = (const float*)d_in[0];
    const float* attn_w = (const float*)d_in[1];
    const float* attn_b = (const float*)d_in[2];
    const float* attn_h = (const float*)d_in[3];
    const float* pool_w = (const float*)d_in[4];
    const float* pool_b = (const float*)d_in[5];
    float* out = (float*)d_out;

    cudaFuncSetAttribute(afm_kernel, cudaFuncAttributeMaxDynamicSharedMemorySize, SMEM_BYTES);

    int B = in_sizes[0] / (FDIM * EDIM);
    afm_kernel<<<B, THREADS, SMEM_BYTES>>>(x, attn_w, attn_b, attn_h, pool_w, pool_b, out);
}

// round 4
// speedup vs baseline: 1.6256x; 1.6256x over previous
#include <cuda_runtime.h>
#include <cstdint>

#define THREADS 160
#define NTILE   136        // 16*17/2 upper-triangle 4x4 tiles
#define FDIM    64
#define EDIM    32

typedef unsigned long long ull;

static __device__ __forceinline__ ull pk2(float lo, float hi) {
    ull r;
    asm("mov.b64 %0, {%1, %2};" : "=l"(r) : "f"(lo), "f"(hi));
    return r;
}
static __device__ __forceinline__ float2 upk2(ull v) {
    float2 r;
    asm("mov.b64 {%0, %1}, %2;" : "=f"(r.x), "=f"(r.y) : "l"(v));
    return r;
}
static __device__ __forceinline__ ull mul2(ull a, ull b) {
    ull d;
    asm("mul.rn.f32x2 %0, %1, %2;" : "=l"(d) : "l"(a), "l"(b));
    return d;
}
static __device__ __forceinline__ ull fma2_(ull a, ull b, ull c) {
    ull d;
    asm("fma.rn.f32x2 %0, %1, %2, %3;" : "=l"(d) : "l"(a), "l"(b), "l"(c));
    return d;
}

__global__ void __launch_bounds__(THREADS, 3)
afm_kernel(const float* __restrict__ x,
           const float* __restrict__ attn_w,
           const float* __restrict__ attn_b,
           const float* __restrict__ attn_h,
           const float* __restrict__ pool_w,
           const float* __restrict__ pool_b,
           float* __restrict__ out)
{
    __shared__ float Xt[EDIM][FDIM + 4];   // Xt[e][f] = x[f,e], padded
    __shared__ float w5[EDIM][8];          // [e][0..3]=attn_w, [e][4]=pool_w
    __shared__ float rmax[5], rse[5], rsq[5];
    __shared__ float bmax;

    const int t = threadIdx.x;
    const int b = blockIdx.x;
    const float* xb = x + (size_t)b * (FDIM * EDIM);

    // ---- load + transpose x[b] (coalesced LDG.128) ----
    for (int q = t; q < 512; q += THREADS) {
        int f  = q >> 3;            // feature 0..63
        int e4 = q & 7;             // group of 4 e
        float4 v = reinterpret_cast<const float4*>(xb)[q];
        Xt[e4 * 4 + 0][f] = v.x;
        Xt[e4 * 4 + 1][f] = v.y;
        Xt[e4 * 4 + 2][f] = v.z;
        Xt[e4 * 4 + 3][f] = v.w;
    }
    if (t < EDIM) {
        float4 wv = reinterpret_cast<const float4*>(attn_w)[t];
        w5[t][0] = wv.x; w5[t][1] = wv.y; w5[t][2] = wv.z; w5[t][3] = wv.w;
        w5[t][4] = pool_w[t];
    }

    // ---- thread -> upper-triangle 4x4 tile (ti <= tj) ----
    int k = (t < NTILE) ? t : (NTILE - 1);
    int ti = (int)((33.0f - sqrtf(1089.0f - 8.0f * (float)k)) * 0.5f);
    while (ti > 0 && (33 * ti - ti * ti) / 2 > k) ti--;
    while ((33 * (ti + 1) - (ti + 1) * (ti + 1)) / 2 <= k) ti++;
    int tj = ti + (k - (33 * ti - ti * ti) / 2);
    const int i0 = ti * 4, j0 = tj * 4;

    __syncthreads();

    // ---- mainloop: P = x_i * x_j (8 mul2), acc_a += w_a * P (40 fma2) ----
    ull acc[5][4][2];
    #pragma unroll
    for (int a = 0; a < 5; a++)
        #pragma unroll
        for (int ii = 0; ii < 4; ii++) { acc[a][ii][0] = 0ull; acc[a][ii][1] = 0ull; }

    #pragma unroll 2
    for (int e = 0; e < EDIM; e++) {
        float4     xiv = *reinterpret_cast<const float4*>(&Xt[e][i0]);
        ulonglong2 xj  = *reinterpret_cast<const ulonglong2*>(&Xt[e][j0]);  // 2 f32x2 direct
        float4     wv  = *reinterpret_cast<const float4*>(&w5[e][0]);
        float      wp  = w5[e][4];

        ull dxi[4] = { pk2(xiv.x, xiv.x), pk2(xiv.y, xiv.y),
                       pk2(xiv.z, xiv.z), pk2(xiv.w, xiv.w) };

        ull P[4][2];
        #pragma unroll
        for (int ii = 0; ii < 4; ii++) {
            P[ii][0] = mul2(dxi[ii], xj.x);
            P[ii][1] = mul2(dxi[ii], xj.y);
        }

        float wa[5] = { wv.x, wv.y, wv.z, wv.w, wp };
        #pragma unroll
        for (int a = 0; a < 5; a++) {
            ull dw = pk2(wa[a], wa[a]);
            #pragma unroll
            for (int ii = 0; ii < 4; ii++) {
                acc[a][ii][0] = fma2_(dw, P[ii][0], acc[a][ii][0]);
                acc[a][ii][1] = fma2_(dw, P[ii][1], acc[a][ii][1]);
            }
        }
    }

    // ---- combine: relu-MLP score, pooled bilinear per pair ----
    const float b0 = attn_b[0], b1 = attn_b[1], b2 = attn_b[2], b3 = attn_b[3];
    const float h0 = attn_h[0], h1 = attn_h[1], h2 = attn_h[2], h3 = attn_h[3];

    float sc[4][4], qc[4][4];
    #pragma unroll
    for (int ii = 0; ii < 4; ii++) {
        #pragma unroll
        for (int jp = 0; jp < 2; jp++) {
            float2 a0 = upk2(acc[0][ii][jp]);
            float2 a1 = upk2(acc[1][ii][jp]);
            float2 a2 = upk2(acc[2][ii][jp]);
            float2 a3 = upk2(acc[3][ii][jp]);
            float2 a4 = upk2(acc[4][ii][jp]);
            sc[ii][jp * 2 + 0] = fmaxf(a0.x + b0, 0.f) * h0 + fmaxf(a1.x + b1, 0.f) * h1
                               + fmaxf(a2.x + b2, 0.f) * h2 + fmaxf(a3.x + b3, 0.f) * h3;
            sc[ii][jp * 2 + 1] = fmaxf(a0.y + b0, 0.f) * h0 + fmaxf(a1.y + b1, 0.f) * h1
                               + fmaxf(a2.y + b2, 0.f) * h2 + fmaxf(a3.y + b3, 0.f) * h3;
            qc[ii][jp * 2 + 0] = a4.x;
            qc[ii][jp * 2 + 1] = a4.y;
        }
    }

    const bool live = (t < NTILE);

    // ---- softmax over i<j cells, fused weighted scalar sum ----
    float lmax = -1e30f;
    #pragma unroll
    for (int ii = 0; ii < 4; ii++)
        #pragma unroll
        for (int jj = 0; jj < 4; jj++)
            if (live && (i0 + ii < j0 + jj)) lmax = fmaxf(lmax, sc[ii][jj]);

    #pragma unroll
    for (int o = 16; o; o >>= 1)
        lmax = fmaxf(lmax, __shfl_xor_sync(0xffffffffu, lmax, o));
    if ((t & 31) == 0) rmax[t >> 5] = lmax;
    __syncthreads();
    if (t == 0) {
        float m = rmax[0];
        #pragma unroll
        for (int i = 1; i < 5; i++) m = fmaxf(m, rmax[i]);
        bmax = m;
    }
    __syncthreads();
    const float m = bmax;

    float se = 0.f, sq = 0.f;
    #pragma unroll
    for (int ii = 0; ii < 4; ii++)
        #pragma unroll
        for (int jj = 0; jj < 4; jj++)
            if (live && (i0 + ii < j0 + jj)) {
                float ex = __expf(sc[ii][jj] - m);
                se += ex;
                sq += ex * qc[ii][jj];
            }

    #pragma unroll
    for (int o = 16; o; o >>= 1) {
        se += __shfl_xor_sync(0xffffffffu, se, o);
        sq += __shfl_xor_sync(0xffffffffu, sq, o);
    }
    if ((t & 31) == 0) { rse[t >> 5] = se; rsq[t >> 5] = sq; }
    __syncthreads();
    if (t == 0) {
        float S = 0.f, Q = 0.f;
        #pragma unroll
        for (int i = 0; i < 5; i++) { S += rse[i]; Q += rsq[i]; }
        out[b] = Q / S + pool_b[0];
    }
}

extern "C" void kernel_launch(void* const* d_in, const int* in_sizes, int n_in,
                              void* d_out, int out_size)
{
    const float* x      = (const float*)d_in[0];
    const float* attn_w = (const float*)d_in[1];
    const float* attn_b = (const float*)d_in[2];
    const float* attn_h = (const float*)d_in[3];
    const float* pool_w = (const float*)d_in[4];
    const float* pool_b = (const float*)d_in[5];
    float* out = (float*)d_out;

    int B = in_sizes[0] / (FDIM * EDIM);
    afm_kernel<<<B, THREADS>>>(x, attn_w, attn_b, attn_h, pool_w, pool_b, out);
}

// round 5
// speedup vs baseline: 2.3859x; 1.4678x over previous
#include <cuda_runtime.h>
#include <cstdint>

#define THREADS   128
#define FDIM      64
#define EDIM      32
#define ROWPAD    40                  // bf16 per row: 32 data + 8 pad = 80 B
#define ROWBYTES  80
#define BUFBYTES  (FDIM * ROWBYTES)   // 5120 B per [64][40] bf16 buffer
#define NBUF      12                  // 0..9 = head*2+{h,l} of y; 10 = xh; 11 = xl
#define SMEM_BYTES (NBUF * BUFBYTES)  // 61440

static __device__ __forceinline__ uint32_t pack_bf16x2(float hi, float lo) {
    uint32_t r;
    asm("cvt.rn.bf16x2.f32 %0, %1, %2;" : "=r"(r) : "f"(hi), "f"(lo));
    return r;
}
static __device__ __forceinline__ void ldsm4(uint32_t* r, uint32_t addr) {
    asm volatile("ldmatrix.sync.aligned.m8n8.x4.shared.b16 {%0,%1,%2,%3}, [%4];"
                 : "=r"(r[0]), "=r"(r[1]), "=r"(r[2]), "=r"(r[3]) : "r"(addr));
}
static __device__ __forceinline__ void mma16816(float* d, const uint32_t* a,
                                                uint32_t b0, uint32_t b1) {
    asm volatile("mma.sync.aligned.m16n8k16.row.col.f32.bf16.bf16.f32 "
                 "{%0,%1,%2,%3}, {%4,%5,%6,%7}, {%8,%9}, {%0,%1,%2,%3};"
                 : "+f"(d[0]), "+f"(d[1]), "+f"(d[2]), "+f"(d[3])
                 : "r"(a[0]), "r"(a[1]), "r"(a[2]), "r"(a[3]), "r"(b0), "r"(b1));
}

__global__ void __launch_bounds__(THREADS, 3)
afm_kernel(const float* __restrict__ x,
           const float* __restrict__ attn_w,
           const float* __restrict__ attn_b,
           const float* __restrict__ attn_h,
           const float* __restrict__ pool_w,
           const float* __restrict__ pool_b,
           float* __restrict__ out)
{
    extern __shared__ __align__(16) char sm[];
    __shared__ float w5[EDIM][8];     // [e][0..3]=attn_w, [e][4]=pool_w
    __shared__ float rmax[4], rse[4], rsq[4];
    __shared__ float bmaxs;

    const int t = threadIdx.x;
    const int b = blockIdx.x;
    const float* xb = x + (size_t)b * (FDIM * EDIM);

    // ================= prologue: split x, build 5 y-tables (bf16 hi/lo) ======
    const int f = t & 63;
    const int h = t >> 6;             // e-half: 0 -> e 0..15, 1 -> e 16..31
    const float* src = xb + f * EDIM + h * 16;
    float4 v4[4];
    #pragma unroll
    for (int q = 0; q < 4; q++) v4[q] = reinterpret_cast<const float4*>(src)[q];

    if (t < EDIM) {
        float4 wv = reinterpret_cast<const float4*>(attn_w)[t];
        w5[t][0] = wv.x; w5[t][1] = wv.y; w5[t][2] = wv.z; w5[t][3] = wv.w;
        w5[t][4] = pool_w[t];
    }
    __syncthreads();

    float v[16];
    #pragma unroll
    for (int q = 0; q < 4; q++) {
        v[q * 4 + 0] = v4[q].x; v[q * 4 + 1] = v4[q].y;
        v[q * 4 + 2] = v4[q].z; v[q * 4 + 3] = v4[q].w;
    }

    #pragma unroll
    for (int c = 0; c < 2; c++) {          // chunk of 8 e (4 bf16x2)
        uint32_t xh4[4], xl4[4], yh4[5][4], yl4[5][4];
        #pragma unroll
        for (int p = 0; p < 4; p++) {
            int ei = c * 8 + p * 2;
            int e  = h * 16 + ei;
            float a0 = v[ei], a1 = v[ei + 1];
            uint32_t u0 = __float_as_uint(a0), u1 = __float_as_uint(a1);
            xh4[p] = __byte_perm(u0, u1, 0x7632);            // {hi16(a1),hi16(a0)}
            float t0 = a0 - __uint_as_float(u0 & 0xFFFF0000u);
            float t1 = a1 - __uint_as_float(u1 & 0xFFFF0000u);
            xl4[p] = pack_bf16x2(t1, t0);
            float4 wr0 = *reinterpret_cast<const float4*>(&w5[e][0]);
            float4 wr1 = *reinterpret_cast<const float4*>(&w5[e + 1][0]);
            float wa0[5] = { wr0.x, wr0.y, wr0.z, wr0.w, w5[e][4] };
            float wa1[5] = { wr1.x, wr1.y, wr1.z, wr1.w, w5[e + 1][4] };
            #pragma unroll
            for (int a = 0; a < 5; a++) {
                float y0 = a0 * wa0[a], y1 = a1 * wa1[a];
                uint32_t q0 = __float_as_uint(y0), q1 = __float_as_uint(y1);
                yh4[a][p] = __byte_perm(q0, q1, 0x7632);
                float g0 = y0 - __uint_as_float(q0 & 0xFFFF0000u);
                float g1 = y1 - __uint_as_float(q1 & 0xFFFF0000u);
                yl4[a][p] = pack_bf16x2(g1, g0);
            }
        }
        int off = f * ROWBYTES + h * 32 + c * 16;
        *reinterpret_cast<uint4*>(sm + 10 * BUFBYTES + off) = *reinterpret_cast<uint4*>(xh4);
        *reinterpret_cast<uint4*>(sm + 11 * BUFBYTES + off) = *reinterpret_cast<uint4*>(xl4);
        #pragma unroll
        for (int a = 0; a < 5; a++) {
            *reinterpret_cast<uint4*>(sm + (2 * a + 0) * BUFBYTES + off) = *reinterpret_cast<uint4*>(yh4[a]);
            *reinterpret_cast<uint4*>(sm + (2 * a + 1) * BUFBYTES + off) = *reinterpret_cast<uint4*>(yl4[a]);
        }
    }
    __syncthreads();

    // ================= mainloop: 20 triangle warp-tiles, 5 per warp ==========
    const int lane = t & 31;
    const int w    = t >> 5;
    const int lg = lane >> 3, lr = lane & 7;
    // A-fragment lane address offset (bytes): rows (lg&1)*8+lr, col half (lg>>1)*8 elems
    const uint32_t a_off = (uint32_t)(((lg & 1) * 8 + lr) * ROWBYTES + (lg >> 1) * 16);
    // B-fragment lane address offset: rows lr, col group lg*8 elems
    const uint32_t b_off = (uint32_t)(lr * ROWBYTES + lg * 16);

    uint32_t smb = (uint32_t)__cvta_generic_to_shared(sm);
    const uint32_t xh_base = smb + 10 * BUFBYTES;
    const uint32_t xl_base = smb + 11 * BUFBYTES;

    const float ba[4] = { attn_b[0], attn_b[1], attn_b[2], attn_b[3] };
    const float ha[4] = { attn_h[0], attn_h[1], attn_h[2], attn_h[3] };

    float sc[5][4], qc[5][4];
    int ti_r[5], tj_r[5];

    #pragma unroll
    for (int k = 0; k < 5; k++) {
        int idx = w + 4 * k;
        int ti, tj;
        if (idx < 8)       { ti = 0; tj = idx; }
        else if (idx < 14) { ti = 1; tj = idx - 6; }
        else if (idx < 18) { ti = 2; tj = idx - 10; }
        else               { ti = 3; tj = idx - 12; }
        ti_r[k] = ti; tj_r[k] = tj;
        const int i0 = ti * 16, j0 = tj * 8;

        uint32_t bh[4], bl[4];
        ldsm4(bh, xh_base + (uint32_t)(j0 * ROWBYTES) + b_off);
        ldsm4(bl, xl_base + (uint32_t)(j0 * ROWBYTES) + b_off);

        const uint32_t arow = smb + (uint32_t)(i0 * ROWBYTES) + a_off;

        float tsc[4] = {0.f, 0.f, 0.f, 0.f};
        #pragma unroll
        for (int a = 0; a < 5; a++) {
            uint32_t yhb = arow + (uint32_t)((2 * a + 0) * BUFBYTES);
            uint32_t ylb = arow + (uint32_t)((2 * a + 1) * BUFBYTES);
            uint32_t ah0[4], ah1[4], al0[4], al1[4];
            ldsm4(ah0, yhb);
            ldsm4(ah1, yhb + 32);    // e cols 16..31
            ldsm4(al0, ylb);
            ldsm4(al1, ylb + 32);

            float d[4] = {0.f, 0.f, 0.f, 0.f};
            mma16816(d, ah0, bh[0], bh[1]);   // yh·xh k0
            mma16816(d, ah1, bh[2], bh[3]);   // yh·xh k1
            mma16816(d, ah0, bl[0], bl[1]);   // yh·xl k0
            mma16816(d, ah1, bl[2], bl[3]);   // yh·xl k1
            mma16816(d, al0, bh[0], bh[1]);   // yl·xh k0
            mma16816(d, al1, bh[2], bh[3]);   // yl·xh k1

            if (a < 4) {
                #pragma unroll
                for (int cc = 0; cc < 4; cc++)
                    tsc[cc] += fmaxf(d[cc] + ba[a], 0.f) * ha[a];
            } else {
                #pragma unroll
                for (int cc = 0; cc < 4; cc++) qc[k][cc] = d[cc];
            }
        }
        #pragma unroll
        for (int cc = 0; cc < 4; cc++) sc[k][cc] = tsc[cc];
    }

    // ================= softmax over live cells (i<j) + weighted pool ========
    float lmax = -1e30f;
    #pragma unroll
    for (int k = 0; k < 5; k++)
        #pragma unroll
        for (int cc = 0; cc < 4; cc++) {
            int i = ti_r[k] * 16 + (lane >> 2) + ((cc >= 2) ? 8 : 0);
            int j = tj_r[k] * 8 + 2 * (lane & 3) + (cc & 1);
            if (i < j) lmax = fmaxf(lmax, sc[k][cc]);
        }
    #pragma unroll
    for (int o = 16; o; o >>= 1)
        lmax = fmaxf(lmax, __shfl_xor_sync(0xffffffffu, lmax, o));
    if (lane == 0) rmax[w] = lmax;
    __syncthreads();
    if (t == 0)
        bmaxs = fmaxf(fmaxf(rmax[0], rmax[1]), fmaxf(rmax[2], rmax[3]));
    __syncthreads();
    const float m = bmaxs;

    float se = 0.f, sq = 0.f;
    #pragma unroll
    for (int k = 0; k < 5; k++)
        #pragma unroll
        for (int cc = 0; cc < 4; cc++) {
            int i = ti_r[k] * 16 + (lane >> 2) + ((cc >= 2) ? 8 : 0);
            int j = tj_r[k] * 8 + 2 * (lane & 3) + (cc & 1);
            if (i < j) {
                float ex = __expf(sc[k][cc] - m);
                se += ex;
                sq += ex * qc[k][cc];
            }
        }
    #pragma unroll
    for (int o = 16; o; o >>= 1) {
        se += __shfl_xor_sync(0xffffffffu, se, o);
        sq += __shfl_xor_sync(0xffffffffu, sq, o);
    }
    if (lane == 0) { rse[w] = se; rsq[w] = sq; }
    __syncthreads();
    if (t == 0) {
        float S = rse[0] + rse[1] + rse[2] + rse[3];
        float Q = rsq[0] + rsq[1] + rsq[2] + rsq[3];
        out[b] = Q / S + pool_b[0];
    }
}

extern "C" void kernel_launch(void* const* d_in, const int* in_sizes, int n_in,
                              void* d_out, int out_size)
{
    const float* x      = (const float*)d_in[0];
    const float* attn_w = (const float*)d_in[1];
    const float* attn_b = (const float*)d_in[2];
    const float* attn_h = (const float*)d_in[3];
    const float* pool_w = (const float*)d_in[4];
    const float* pool_b = (const float*)d_in[5];
    float* out = (float*)d_out;

    cudaFuncSetAttribute(afm_kernel, cudaFuncAttributeMaxDynamicSharedMemorySize, SMEM_BYTES);

    int B = in_sizes[0] / (FDIM * EDIM);
    afm_kernel<<<B, THREADS, SMEM_BYTES>>>(x, attn_w, attn_b, attn_h, pool_w, pool_b, out);
}